// round 9
// baseline (speedup 1.0000x reference)
#include <cuda_runtime.h>
#include <cstdint>

#define SLOTS  (1<<17)
#define NBUCK  (1<<16)
#define MMAX   SLOTS
#define NMAX   (1<<20)

// ---------------- device scratch (static, no allocation) ----------------
__device__ int                g_headmin[SLOTS];
__device__ int                g_rank[SLOTS];
__device__ int                g_headof[MMAX];
__device__ int                g_cluster[NMAX];
__device__ unsigned long long g_keys_raw[MMAX];
__device__ unsigned long long g_keys_sorted[MMAX];
__device__ int                g_hist[NBUCK];
__device__ int                g_off[NBUCK];
__device__ int                g_off2[NBUCK];
__device__ float4             g_Wt4[128*256/4];   // W transposed [k][c], 16B aligned

// order-preserving float<->uint encode (total order, works for negatives)
__device__ __forceinline__ unsigned int encf(float f){
    unsigned int b = __float_as_uint(f);
    return (b & 0x80000000u) ? ~b : (b | 0x80000000u);
}
__device__ __forceinline__ float decf(unsigned int e){
    unsigned int b = (e & 0x80000000u) ? (e & 0x7FFFFFFFu) : ~e;
    return __uint_as_float(b);
}

// ---------------- setup ----------------
// i covers max(SLOTS, 3*M); zeroes slot table, hist, coord accum, count accum
__global__ void k_init(float* __restrict__ out, int M, int N){
    int i = blockIdx.x*blockDim.x + threadIdx.x;
    if (i < SLOTS) g_headmin[i] = 0x7fffffff;
    if (i < NBUCK) g_hist[i] = 0;
    size_t Ms = (size_t)M;
    if (i < 3*M) out[256*Ms + i] = 0.f;              // coord_p accumulators
    if (i < M)   out[268*Ms + (size_t)N + i] = 0.f;  // count accumulators (batch_p slot)
}

// zero x region [0, 256*M) floats = M*64 uint4 (encoded 0 == -NaN-low, below all finite)
__global__ void k_zerox(uint4* __restrict__ x, size_t n4){
    size_t i = (size_t)blockIdx.x*blockDim.x + threadIdx.x;
    size_t stride = (size_t)gridDim.x*blockDim.x;
    uint4 z = make_uint4(0u,0u,0u,0u);
    for (; i < n4; i += stride) x[i] = z;
}

__global__ void k_wt(const float* __restrict__ W){
    int t = blockIdx.x*blockDim.x + threadIdx.x;
    if (t < 128*256){
        int c = t & 255, k = t >> 8;
        ((float*)g_Wt4)[k*256 + c] = W[c*128 + k];
    }
}

__global__ void k_headmin(const int* __restrict__ code0, int Npts){
    int i = blockIdx.x*blockDim.x + threadIdx.x;
    if (i >= Npts) return;
    int c0 = code0[i] >> 3;
    if (c0 >= 0 && c0 < SLOTS) atomicMin(&g_headmin[c0], i);
}

// single-block scan over slot occupancy -> g_rank, g_headof
__global__ void k_scan_slots(){
    __shared__ int ss[1024];
    int t = threadIdx.x;
    int base = t * (SLOTS/1024);
    int c = 0;
    for (int i = 0; i < SLOTS/1024; i++) c += (g_headmin[base+i] != 0x7fffffff);
    ss[t] = c; __syncthreads();
    int mycnt = c;
    for (int off = 1; off < 1024; off <<= 1){
        int v = (t >= off) ? ss[t-off] : 0;
        __syncthreads();
        ss[t] += v;
        __syncthreads();
    }
    int run = ss[t] - mycnt;
    for (int i = 0; i < SLOTS/1024; i++){
        int s = base + i;
        int h = g_headmin[s];
        if (h != 0x7fffffff){
            g_rank[s] = run;
            g_headof[run] = h;
            run++;
        }
    }
}

__global__ void k_points(const int* __restrict__ code0,
                         const float* __restrict__ coord,
                         float* __restrict__ out, int M, int Npts){
    int i = blockIdx.x*blockDim.x + threadIdx.x;
    if (i >= Npts) return;
    int c0 = code0[i] >> 3;
    int m = 0;
    if (c0 >= 0 && c0 < SLOTS) m = g_rank[c0];
    if (m < 0 || m >= MMAX) m = 0;
    g_cluster[i] = m;
    size_t Ms = (size_t)M;
    out[268*Ms + (size_t)i] = (float)m;              // cluster output
    if (m < M){
        atomicAdd(&out[268*Ms + (size_t)Npts + m], 1.0f);   // count
        size_t ci = 3ull*(size_t)i;
        atomicAdd(&out[256*Ms + 3*(size_t)m+0], coord[ci+0]);
        atomicAdd(&out[256*Ms + 3*(size_t)m+1], coord[ci+1]);
        atomicAdd(&out[256*Ms + 3*(size_t)m+2], coord[ci+2]);
    }
}

__global__ void k_heads(const int* __restrict__ code0,
                        const int* __restrict__ code1,
                        const int* __restrict__ grid_coord,
                        const int* __restrict__ batch,
                        float* __restrict__ out, int M, int Npts){
    int m = blockIdx.x*blockDim.x + threadIdx.x;
    if (m >= M || m >= MMAX) return;
    int h = g_headof[m];
    if (h < 0 || h >= Npts) return;
    size_t Ms = (size_t)M;
    float cf = out[268*Ms + (size_t)Npts + m];        // count (read BEFORE overwrite)
    float inv = 1.0f / cf;
    out[256*Ms + 3*(size_t)m+0] *= inv;               // coord_p = sum / count
    out[256*Ms + 3*(size_t)m+1] *= inv;
    out[256*Ms + 3*(size_t)m+2] *= inv;
    size_t hb = 3ull*(size_t)h;
    out[259*Ms + 3*(size_t)m+0] = (float)(grid_coord[hb+0] >> 1);  // grid_p
    out[259*Ms + 3*(size_t)m+1] = (float)(grid_coord[hb+1] >> 1);
    out[259*Ms + 3*(size_t)m+2] = (float)(grid_coord[hb+2] >> 1);
    int c0h = code0[h] >> 3;
    int c1h = code1[h] >> 3;
    out[262*Ms + m] = (float)c0h;                     // code_h row0
    out[263*Ms + m] = (float)c1h;                     // code_h row1
    out[264*Ms + m] = (float)m;                       // order row0 (identity)
    out[266*Ms + m] = (float)m;                       // inverse row0 (identity)
    out[268*Ms + (size_t)Npts + m] = (float)batch[h]; // batch_p (overwrites count)
    if (c1h >= 0){
        int b = c1h >> 11;                            // c1h < 2^27 -> 16-bit bucket
        if (b < NBUCK){
            g_keys_raw[m] = ((unsigned long long)(unsigned)c1h << 20) | (unsigned)m;
            atomicAdd(&g_hist[b], 1);
        }
    }
}

__global__ void k_scan_hist(){
    __shared__ int ss[1024];
    int t = threadIdx.x;
    int base = t * (NBUCK/1024);
    int c = 0;
    for (int i = 0; i < NBUCK/1024; i++) c += g_hist[base+i];
    ss[t] = c; __syncthreads();
    int mycnt = c;
    for (int off = 1; off < 1024; off <<= 1){
        int v = (t >= off) ? ss[t-off] : 0;
        __syncthreads();
        ss[t] += v;
        __syncthreads();
    }
    int run = ss[t] - mycnt;
    for (int i = 0; i < NBUCK/1024; i++){
        int s = base + i;
        g_off[s]  = run;
        g_off2[s] = run;
        run += g_hist[s];
    }
}

__global__ void k_scatter(int M){
    int m = blockIdx.x*blockDim.x + threadIdx.x;
    if (m >= M || m >= MMAX) return;
    unsigned long long key = g_keys_raw[m];
    int b = (int)(key >> 31);                          // (c1h<<20)>>31 == c1h>>11
    if (b < 0 || b >= NBUCK) return;
    int pos = atomicAdd(&g_off2[b], 1);
    if (pos >= 0 && pos < MMAX) g_keys_sorted[pos] = key;
}

// per-bucket insertion sort (shared staging), writes order/inverse row 1
__global__ void k_bsort(float* __restrict__ out, int M){
    __shared__ unsigned long long sb[40*128];
    int t  = blockIdx.x*128 + threadIdx.x;
    int tl = threadIdx.x;
    if (t >= NBUCK) return;
    int start = g_off[t];
    int cnt   = g_hist[t];
    if (cnt <= 0 || start < 0 || start >= MMAX) return;
    if (cnt > MMAX - start) cnt = MMAX - start;
    size_t offOrd = 265ull*(size_t)M;   // order row1
    size_t offInv = 267ull*(size_t)M;   // inverse row1
    if (cnt <= 40){
        for (int j = 0; j < cnt; j++) sb[j*128+tl] = g_keys_sorted[start+j];
        for (int a = 1; a < cnt; a++){
            unsigned long long x = sb[a*128+tl];
            int b2 = a-1;
            while (b2 >= 0 && sb[b2*128+tl] > x){ sb[(b2+1)*128+tl] = sb[b2*128+tl]; b2--; }
            sb[(b2+1)*128+tl] = x;
        }
        for (int j = 0; j < cnt; j++){
            unsigned long long key = sb[j*128+tl];
            int m = (int)(key & 0xFFFFFull);
            int p = start + j;
            if (p < M)            out[offOrd + p] = (float)m;
            if (m < M && m >= 0)  out[offInv + m] = (float)p;
        }
    } else {
        for (int a = 0; a < cnt; a++){
            int best = a; unsigned long long bk = g_keys_sorted[start+a];
            for (int j = a+1; j < cnt; j++){
                unsigned long long kj = g_keys_sorted[start+j];
                if (kj < bk){ bk = kj; best = j; }
            }
            unsigned long long tmp = g_keys_sorted[start+a];
            g_keys_sorted[start+a] = bk;
            g_keys_sorted[start+best] = tmp;
            int m = (int)(bk & 0xFFFFFull);
            if (start + a < M)    out[offOrd + start + a] = (float)m;
            if (m < M && m >= 0)  out[offInv + m] = (float)(start + a);
        }
    }
}

// ---------------- fused GEMM (proj = feat @ W^T + b) + segment-max ----------------
// 256 threads, block tile 64 rows x 256 cols, K chunked 4 x 32 (<=40KB smem).
// 8x8 micro-tile per thread, plain fmaf; epilogue atomicMax into d_out x region.
__global__ __launch_bounds__(256) void k_gemm(const float* __restrict__ feat,
                                              const float* __restrict__ bias,
                                              unsigned int* __restrict__ xenc,
                                              int M, int Npts){
    __shared__ float4 sF4[64*8];      // 64 rows x 32 k   = 8KB
    __shared__ float4 sW4[32*64];     // 32 k x 256 c     = 32KB
    float* sF = (float*)sF4;
    int tid  = threadIdx.x;
    int row0 = blockIdx.x * 64;
    int warp = tid >> 5, lane = tid & 31;
    int rb = warp * 8;
    int cb = lane * 8;

    float acc[8][8];
#pragma unroll
    for (int i = 0; i < 8; i++)
#pragma unroll
        for (int c = 0; c < 8; c++) acc[i][c] = 0.f;

    const float4* featv = (const float4*)feat;

    for (int kc = 0; kc < 4; kc++){
        __syncthreads();
#pragma unroll
        for (int it = 0; it < 2; it++){
            int i = tid + it*256;
            int rl = i >> 3, v = i & 7;
            sF4[i] = featv[(size_t)(row0 + rl)*32 + kc*8 + v];
        }
#pragma unroll
        for (int it = 0; it < 8; it++){
            int i = tid + it*256;
            int kl = i >> 6, v = i & 63;
            sW4[i] = g_Wt4[(size_t)(kc*32 + kl)*64 + v];
        }
        __syncthreads();

#pragma unroll 8
        for (int kk = 0; kk < 32; kk++){
            float4 w0 = sW4[kk*64 + lane*2 + 0];
            float4 w1 = sW4[kk*64 + lane*2 + 1];
            float a[8];
#pragma unroll
            for (int i = 0; i < 8; i++) a[i] = sF[(rb+i)*32 + kk];
#pragma unroll
            for (int i = 0; i < 8; i++){
                acc[i][0] = fmaf(a[i], w0.x, acc[i][0]);
                acc[i][1] = fmaf(a[i], w0.y, acc[i][1]);
                acc[i][2] = fmaf(a[i], w0.z, acc[i][2]);
                acc[i][3] = fmaf(a[i], w0.w, acc[i][3]);
                acc[i][4] = fmaf(a[i], w1.x, acc[i][4]);
                acc[i][5] = fmaf(a[i], w1.y, acc[i][5]);
                acc[i][6] = fmaf(a[i], w1.z, acc[i][6]);
                acc[i][7] = fmaf(a[i], w1.w, acc[i][7]);
            }
        }
    }

    float bb[8];
#pragma unroll
    for (int c = 0; c < 8; c++) bb[c] = bias[cb + c];

#pragma unroll
    for (int i = 0; i < 8; i++){
        int r = row0 + rb + i;
        if (r >= Npts) continue;
        int m = g_cluster[r];
        if (m < 0 || m >= M) continue;
        unsigned int* dstp = xenc + (size_t)m*256 + cb;
#pragma unroll
        for (int c = 0; c < 8; c++){
            atomicMax(dstp + c, encf(acc[i][c] + bb[c]));
        }
    }
}

// ---------------- LayerNorm + exact GELU, in place over x region ----------------
__global__ void k_ln(float* __restrict__ out,
                     const float* __restrict__ gamma,
                     const float* __restrict__ beta, int M){
    int w = threadIdx.x >> 5, lane = threadIdx.x & 31;
    int m = blockIdx.x*8 + w;
    if (m >= M) return;
    const unsigned int* src = (const unsigned int*)out + (size_t)m*256;
    float v[8]; float s = 0.f;
#pragma unroll
    for (int j = 0; j < 8; j++){ v[j] = decf(src[lane + 32*j]); s += v[j]; }
#pragma unroll
    for (int o = 16; o; o >>= 1) s += __shfl_xor_sync(0xffffffffu, s, o);
    float mu = s * (1.f/256.f);
    float q = 0.f;
#pragma unroll
    for (int j = 0; j < 8; j++){ float d = v[j]-mu; q += d*d; }
#pragma unroll
    for (int o = 16; o; o >>= 1) q += __shfl_xor_sync(0xffffffffu, q, o);
    float inv = rsqrtf(q*(1.f/256.f) + 1e-5f);
#pragma unroll
    for (int j = 0; j < 8; j++){
        int c = lane + 32*j;
        float y = (v[j]-mu)*inv*gamma[c] + beta[c];
        out[(size_t)m*256 + c] = 0.5f*y*(1.f + erff(y*0.70710678118654752f));
    }
}

// ---------------- launch ----------------
extern "C" void kernel_launch(void* const* d_in, const int* in_sizes, int n_in,
                              void* d_out, int out_size){
    const float* feat  = (const float*)d_in[0];
    const float* coord = (const float*)d_in[1];
    const int*   gridc = (const int*)d_in[2];
    const int*   scode = (const int*)d_in[3];    // int32 (JAX x64 disabled truncation)
    const int*   batch = (const int*)d_in[4];
    int iW = 6;
    for (int i = 5; i < n_in; i++) if (in_sizes[i] == 256*128){ iW = i; break; }
    const float* W     = (const float*)d_in[iW];
    const float* bias  = (const float*)d_in[iW+1];
    const float* gamma = (const float*)d_in[iW+2];
    const float* beta  = (const float*)d_in[iW+3];

    int N = in_sizes[0] / 128;
    int M = (out_size - N) / 269;
    float* out = (float*)d_out;
    const int* code0 = scode;
    const int* code1 = scode + N;

    int Tinit = 3*M > SLOTS ? 3*M : SLOTS;
    k_init<<<(Tinit+255)/256, 256>>>(out, M, N);
    k_zerox<<<2048, 256>>>((uint4*)d_out, (size_t)M*64);
    k_wt<<<128, 256>>>(W);
    k_headmin<<<(N+255)/256, 256>>>(code0, N);
    k_scan_slots<<<1, 1024>>>();
    k_points<<<(N+255)/256, 256>>>(code0, coord, out, M, N);
    k_heads<<<(M+255)/256, 256>>>(code0, code1, gridc, batch, out, M, N);
    k_scan_hist<<<1, 1024>>>();
    k_scatter<<<(M+255)/256, 256>>>(M);
    k_bsort<<<NBUCK/128, 128>>>(out, M);
    k_gemm<<<(N+63)/64, 256>>>(feat, bias, (unsigned int*)d_out, M, N);
    k_ln<<<(M+7)/8, 256>>>(out, gamma, beta, M);
}

// round 10
// speedup vs baseline: 1.0306x; 1.0306x over previous
#include <cuda_runtime.h>
#include <cstdint>

#define SLOTS  (1<<17)
#define NBUCK  (1<<16)
#define MMAX   SLOTS
#define NMAX   (1<<20)

// ---------------- device scratch (static, no allocation) ----------------
__device__ int                g_headmin[SLOTS];
__device__ int                g_rank[SLOTS];
__device__ int                g_headof[MMAX];
__device__ int                g_cluster[NMAX];
__device__ unsigned long long g_keys_raw[MMAX];
__device__ unsigned long long g_keys_sorted[MMAX];
__device__ int                g_hist[NBUCK];
__device__ int                g_off[NBUCK];
__device__ int                g_off2[NBUCK];
__device__ float4             g_Wt4[128*256/4];   // W transposed [k][c], 16B aligned

// order-preserving float<->uint encode (total order, works for negatives)
__device__ __forceinline__ unsigned int encf(float f){
    unsigned int b = __float_as_uint(f);
    return (b & 0x80000000u) ? ~b : (b | 0x80000000u);
}
__device__ __forceinline__ float decf(unsigned int e){
    unsigned int b = (e & 0x80000000u) ? (e & 0x7FFFFFFFu) : ~e;
    return __uint_as_float(b);
}

// ---------------- setup ----------------
__global__ void k_init(float* __restrict__ out, int M, int N){
    int i = blockIdx.x*blockDim.x + threadIdx.x;
    if (i < SLOTS) g_headmin[i] = 0x7fffffff;
    if (i < NBUCK) g_hist[i] = 0;
    size_t Ms = (size_t)M;
    if (i < 3*M) out[256*Ms + i] = 0.f;              // coord_p accumulators
    if (i < M)   out[268*Ms + (size_t)N + i] = 0.f;  // count accumulators (batch_p slot)
}

// zero x region [0, 256*M) floats = M*64 uint4 (encoded 0 sorts below all finite)
__global__ void k_zerox(uint4* __restrict__ x, size_t n4){
    size_t i = (size_t)blockIdx.x*blockDim.x + threadIdx.x;
    size_t stride = (size_t)gridDim.x*blockDim.x;
    uint4 z = make_uint4(0u,0u,0u,0u);
    for (; i < n4; i += stride) x[i] = z;
}

__global__ void k_wt(const float* __restrict__ W){
    int t = blockIdx.x*blockDim.x + threadIdx.x;
    if (t < 128*256){
        int c = t & 255, k = t >> 8;
        ((float*)g_Wt4)[k*256 + c] = W[c*128 + k];
    }
}

__global__ void k_headmin(const int* __restrict__ code0, int Npts){
    int i = blockIdx.x*blockDim.x + threadIdx.x;
    if (i >= Npts) return;
    int c0 = code0[i] >> 3;
    if (c0 >= 0 && c0 < SLOTS) atomicMin(&g_headmin[c0], i);
}

// single-block scan over slot occupancy -> g_rank, g_headof
__global__ void k_scan_slots(){
    __shared__ int ss[1024];
    int t = threadIdx.x;
    int base = t * (SLOTS/1024);
    int c = 0;
    for (int i = 0; i < SLOTS/1024; i++) c += (g_headmin[base+i] != 0x7fffffff);
    ss[t] = c; __syncthreads();
    int mycnt = c;
    for (int off = 1; off < 1024; off <<= 1){
        int v = (t >= off) ? ss[t-off] : 0;
        __syncthreads();
        ss[t] += v;
        __syncthreads();
    }
    int run = ss[t] - mycnt;
    for (int i = 0; i < SLOTS/1024; i++){
        int s = base + i;
        int h = g_headmin[s];
        if (h != 0x7fffffff){
            g_rank[s] = run;
            g_headof[run] = h;
            run++;
        }
    }
}

__global__ void k_points(const int* __restrict__ code0,
                         const float* __restrict__ coord,
                         float* __restrict__ out, int M, int Npts){
    int i = blockIdx.x*blockDim.x + threadIdx.x;
    if (i >= Npts) return;
    int c0 = code0[i] >> 3;
    int m = 0;
    if (c0 >= 0 && c0 < SLOTS) m = g_rank[c0];
    if (m < 0 || m >= MMAX) m = 0;
    g_cluster[i] = m;
    size_t Ms = (size_t)M;
    out[268*Ms + (size_t)i] = (float)m;              // cluster output
    if (m < M){
        atomicAdd(&out[268*Ms + (size_t)Npts + m], 1.0f);   // count
        size_t ci = 3ull*(size_t)i;
        atomicAdd(&out[256*Ms + 3*(size_t)m+0], coord[ci+0]);
        atomicAdd(&out[256*Ms + 3*(size_t)m+1], coord[ci+1]);
        atomicAdd(&out[256*Ms + 3*(size_t)m+2], coord[ci+2]);
    }
}

__global__ void k_heads(const int* __restrict__ code0,
                        const int* __restrict__ code1,
                        const int* __restrict__ grid_coord,
                        const int* __restrict__ batch,
                        float* __restrict__ out, int M, int Npts){
    int m = blockIdx.x*blockDim.x + threadIdx.x;
    if (m >= M || m >= MMAX) return;
    int h = g_headof[m];
    if (h < 0 || h >= Npts) return;
    size_t Ms = (size_t)M;
    float cf = out[268*Ms + (size_t)Npts + m];        // count (read BEFORE overwrite)
    float inv = 1.0f / cf;
    out[256*Ms + 3*(size_t)m+0] *= inv;               // coord_p = sum / count
    out[256*Ms + 3*(size_t)m+1] *= inv;
    out[256*Ms + 3*(size_t)m+2] *= inv;
    size_t hb = 3ull*(size_t)h;
    out[259*Ms + 3*(size_t)m+0] = (float)(grid_coord[hb+0] >> 1);  // grid_p
    out[259*Ms + 3*(size_t)m+1] = (float)(grid_coord[hb+1] >> 1);
    out[259*Ms + 3*(size_t)m+2] = (float)(grid_coord[hb+2] >> 1);
    int c0h = code0[h] >> 3;
    int c1h = code1[h] >> 3;
    out[262*Ms + m] = (float)c0h;                     // code_h row0
    out[263*Ms + m] = (float)c1h;                     // code_h row1
    out[264*Ms + m] = (float)m;                       // order row0 (identity)
    out[266*Ms + m] = (float)m;                       // inverse row0 (identity)
    out[268*Ms + (size_t)Npts + m] = (float)batch[h]; // batch_p (overwrites count)
    if (c1h >= 0){
        int b = c1h >> 11;                            // c1h < 2^27 -> 16-bit bucket
        if (b < NBUCK){
            g_keys_raw[m] = ((unsigned long long)(unsigned)c1h << 20) | (unsigned)m;
            atomicAdd(&g_hist[b], 1);
        }
    }
}

__global__ void k_scan_hist(){
    __shared__ int ss[1024];
    int t = threadIdx.x;
    int base = t * (NBUCK/1024);
    int c = 0;
    for (int i = 0; i < NBUCK/1024; i++) c += g_hist[base+i];
    ss[t] = c; __syncthreads();
    int mycnt = c;
    for (int off = 1; off < 1024; off <<= 1){
        int v = (t >= off) ? ss[t-off] : 0;
        __syncthreads();
        ss[t] += v;
        __syncthreads();
    }
    int run = ss[t] - mycnt;
    for (int i = 0; i < NBUCK/1024; i++){
        int s = base + i;
        g_off[s]  = run;
        g_off2[s] = run;
        run += g_hist[s];
    }
}

__global__ void k_scatter(int M){
    int m = blockIdx.x*blockDim.x + threadIdx.x;
    if (m >= M || m >= MMAX) return;
    unsigned long long key = g_keys_raw[m];
    int b = (int)(key >> 31);                          // (c1h<<20)>>31 == c1h>>11
    if (b < 0 || b >= NBUCK) return;
    int pos = atomicAdd(&g_off2[b], 1);
    if (pos >= 0 && pos < MMAX) g_keys_sorted[pos] = key;
}

// per-bucket insertion sort (shared staging), writes order/inverse row 1
__global__ void k_bsort(float* __restrict__ out, int M){
    __shared__ unsigned long long sb[40*128];
    int t  = blockIdx.x*128 + threadIdx.x;
    int tl = threadIdx.x;
    if (t >= NBUCK) return;
    int start = g_off[t];
    int cnt   = g_hist[t];
    if (cnt <= 0 || start < 0 || start >= MMAX) return;
    if (cnt > MMAX - start) cnt = MMAX - start;
    size_t offOrd = 265ull*(size_t)M;   // order row1
    size_t offInv = 267ull*(size_t)M;   // inverse row1
    if (cnt <= 40){
        for (int j = 0; j < cnt; j++) sb[j*128+tl] = g_keys_sorted[start+j];
        for (int a = 1; a < cnt; a++){
            unsigned long long x = sb[a*128+tl];
            int b2 = a-1;
            while (b2 >= 0 && sb[b2*128+tl] > x){ sb[(b2+1)*128+tl] = sb[b2*128+tl]; b2--; }
            sb[(b2+1)*128+tl] = x;
        }
        for (int j = 0; j < cnt; j++){
            unsigned long long key = sb[j*128+tl];
            int m = (int)(key & 0xFFFFFull);
            int p = start + j;
            if (p < M)            out[offOrd + p] = (float)m;
            if (m < M && m >= 0)  out[offInv + m] = (float)p;
        }
    } else {
        for (int a = 0; a < cnt; a++){
            int best = a; unsigned long long bk = g_keys_sorted[start+a];
            for (int j = a+1; j < cnt; j++){
                unsigned long long kj = g_keys_sorted[start+j];
                if (kj < bk){ bk = kj; best = j; }
            }
            unsigned long long tmp = g_keys_sorted[start+a];
            g_keys_sorted[start+a] = bk;
            g_keys_sorted[start+best] = tmp;
            int m = (int)(bk & 0xFFFFFull);
            if (start + a < M)    out[offOrd + start + a] = (float)m;
            if (m < M && m >= 0)  out[offInv + m] = (float)(start + a);
        }
    }
}

// ---------------- fused GEMM (proj = feat @ W^T + b) + segment-max ----------------
// 256 threads, block tile 64 rows x 256 cols, K chunked 4 x 32 (<=40KB smem).
// 8x8 micro-tile per thread; mainloop uses packed fma.rn.f32x2 (sm_103a):
// 2 fp32 FMAs per instruction -> halves the fma-pipe issue count.
__global__ __launch_bounds__(256) void k_gemm(const float* __restrict__ feat,
                                              const float* __restrict__ bias,
                                              unsigned int* __restrict__ xenc,
                                              int M, int Npts){
    __shared__ float4 sF4[64*8];      // 64 rows x 32 k   = 8KB
    __shared__ float4 sW4[32*64];     // 32 k x 256 c     = 32KB
    float* sF = (float*)sF4;
    float* sW = (float*)sW4;
    int tid  = threadIdx.x;
    int row0 = blockIdx.x * 64;
    int warp = tid >> 5, lane = tid & 31;
    int rb = warp * 8;
    int cb = lane * 8;

    // acc[i][p] = packed pair of fp32 accumulators (cols cb+2p, cb+2p+1)
    unsigned long long acc[8][4];
#pragma unroll
    for (int i = 0; i < 8; i++)
#pragma unroll
        for (int p = 0; p < 4; p++) acc[i][p] = 0ull;

    const float4* featv = (const float4*)feat;

    for (int kc = 0; kc < 4; kc++){
        __syncthreads();
#pragma unroll
        for (int it = 0; it < 2; it++){
            int i = tid + it*256;
            int rl = i >> 3, v = i & 7;
            sF4[i] = featv[(size_t)(row0 + rl)*32 + kc*8 + v];
        }
#pragma unroll
        for (int it = 0; it < 8; it++){
            int i = tid + it*256;
            int kl = i >> 6, v = i & 63;
            sW4[i] = g_Wt4[(size_t)(kc*32 + kl)*64 + v];
        }
        __syncthreads();

#pragma unroll 8
        for (int kk = 0; kk < 32; kk++){
            // 8 weight cols as 4 packed pairs (two LDS128 from 32B-aligned addr)
            const ulonglong2* wrow = (const ulonglong2*)&sW[kk*256 + cb];
            ulonglong2 wa = wrow[0];   // cols cb+0..3
            ulonglong2 wb = wrow[1];   // cols cb+4..7
#pragma unroll
            for (int i = 0; i < 8; i++){
                float fv = sF[(rb+i)*32 + kk];          // broadcast LDS
                unsigned long long fd;
                asm("mov.b64 %0, {%1, %1};" : "=l"(fd) : "f"(fv));
                asm("fma.rn.f32x2 %0, %1, %2, %0;" : "+l"(acc[i][0]) : "l"(fd), "l"(wa.x));
                asm("fma.rn.f32x2 %0, %1, %2, %0;" : "+l"(acc[i][1]) : "l"(fd), "l"(wa.y));
                asm("fma.rn.f32x2 %0, %1, %2, %0;" : "+l"(acc[i][2]) : "l"(fd), "l"(wb.x));
                asm("fma.rn.f32x2 %0, %1, %2, %0;" : "+l"(acc[i][3]) : "l"(fd), "l"(wb.y));
            }
        }
    }

    float bb[8];
#pragma unroll
    for (int c = 0; c < 8; c++) bb[c] = bias[cb + c];

#pragma unroll
    for (int i = 0; i < 8; i++){
        int r = row0 + rb + i;
        if (r >= Npts) continue;
        int m = g_cluster[r];
        if (m < 0 || m >= M) continue;
        unsigned int* dstp = xenc + (size_t)m*256 + cb;
#pragma unroll
        for (int p = 0; p < 4; p++){
            float lo, hi;
            asm("mov.b64 {%0, %1}, %2;" : "=f"(lo), "=f"(hi) : "l"(acc[i][p]));
            atomicMax(dstp + 2*p,     encf(lo + bb[2*p]));
            atomicMax(dstp + 2*p + 1, encf(hi + bb[2*p+1]));
        }
    }
}

// ---------------- LayerNorm + exact GELU, in place over x region ----------------
__global__ void k_ln(float* __restrict__ out,
                     const float* __restrict__ gamma,
                     const float* __restrict__ beta, int M){
    int w = threadIdx.x >> 5, lane = threadIdx.x & 31;
    int m = blockIdx.x*8 + w;
    if (m >= M) return;
    const unsigned int* src = (const unsigned int*)out + (size_t)m*256;
    float v[8]; float s = 0.f;
#pragma unroll
    for (int j = 0; j < 8; j++){ v[j] = decf(src[lane + 32*j]); s += v[j]; }
#pragma unroll
    for (int o = 16; o; o >>= 1) s += __shfl_xor_sync(0xffffffffu, s, o);
    float mu = s * (1.f/256.f);
    float q = 0.f;
#pragma unroll
    for (int j = 0; j < 8; j++){ float d = v[j]-mu; q += d*d; }
#pragma unroll
    for (int o = 16; o; o >>= 1) q += __shfl_xor_sync(0xffffffffu, q, o);
    float inv = rsqrtf(q*(1.f/256.f) + 1e-5f);
#pragma unroll
    for (int j = 0; j < 8; j++){
        int c = lane + 32*j;
        float y = (v[j]-mu)*inv*gamma[c] + beta[c];
        out[(size_t)m*256 + c] = 0.5f*y*(1.f + erff(y*0.70710678118654752f));
    }
}

// ---------------- launch ----------------
extern "C" void kernel_launch(void* const* d_in, const int* in_sizes, int n_in,
                              void* d_out, int out_size){
    const float* feat  = (const float*)d_in[0];
    const float* coord = (const float*)d_in[1];
    const int*   gridc = (const int*)d_in[2];
    const int*   scode = (const int*)d_in[3];    // int32 (JAX x64-disabled truncation)
    const int*   batch = (const int*)d_in[4];
    int iW = 6;
    for (int i = 5; i < n_in; i++) if (in_sizes[i] == 256*128){ iW = i; break; }
    const float* W     = (const float*)d_in[iW];
    const float* bias  = (const float*)d_in[iW+1];
    const float* gamma = (const float*)d_in[iW+2];
    const float* beta  = (const float*)d_in[iW+3];

    int N = in_sizes[0] / 128;
    int M = (out_size - N) / 269;
    float* out = (float*)d_out;
    const int* code0 = scode;
    const int* code1 = scode + N;

    int Tinit = 3*M > SLOTS ? 3*M : SLOTS;
    k_init<<<(Tinit+255)/256, 256>>>(out, M, N);
    k_zerox<<<2048, 256>>>((uint4*)d_out, (size_t)M*64);
    k_wt<<<128, 256>>>(W);
    k_headmin<<<(N+255)/256, 256>>>(code0, N);
    k_scan_slots<<<1, 1024>>>();
    k_points<<<(N+255)/256, 256>>>(code0, coord, out, M, N);
    k_heads<<<(M+255)/256, 256>>>(code0, code1, gridc, batch, out, M, N);
    k_scan_hist<<<1, 1024>>>();
    k_scatter<<<(M+255)/256, 256>>>(M);
    k_bsort<<<NBUCK/128, 128>>>(out, M);
    k_gemm<<<(N+63)/64, 256>>>(feat, bias, (unsigned int*)d_out, M, N);
    k_ln<<<(M+7)/8, 256>>>(out, gamma, beta, M);
}

// round 12
// speedup vs baseline: 2.1846x; 2.1199x over previous
#include <cuda_runtime.h>
#include <cuda_bf16.h>
#include <cstdint>

#define SLOTS  (1<<17)
#define NBUCK  (1<<16)
#define MMAX   SLOTS
#define NMAX   (1<<20)

// ---------------- device scratch (static, no allocation) ----------------
__device__ int                g_headmin[SLOTS];
__device__ int                g_rank[SLOTS];
__device__ int                g_headof[MMAX];
__device__ int                g_cluster[NMAX];
__device__ unsigned long long g_keys_raw[MMAX];
__device__ unsigned long long g_keys_sorted[MMAX];
__device__ int                g_hist[NBUCK];
__device__ int                g_off[NBUCK];
__device__ int                g_off2[NBUCK];
__device__ __nv_bfloat16      g_Whi[256*128];     // W hi split, [c][k]
__device__ __nv_bfloat16      g_Wlo[256*128];     // W lo split, [c][k]

// order-preserving float<->uint encode (total order, works for negatives)
__device__ __forceinline__ unsigned int encf(float f){
    unsigned int b = __float_as_uint(f);
    return (b & 0x80000000u) ? ~b : (b | 0x80000000u);
}
__device__ __forceinline__ float decf(unsigned int e){
    unsigned int b = (e & 0x80000000u) ? (e & 0x7FFFFFFFu) : ~e;
    return __uint_as_float(b);
}

// ---------------- setup ----------------
__global__ void k_init(float* __restrict__ out, int M, int N){
    int i = blockIdx.x*blockDim.x + threadIdx.x;
    if (i < SLOTS) g_headmin[i] = 0x7fffffff;
    if (i < NBUCK) g_hist[i] = 0;
    size_t Ms = (size_t)M;
    if (i < 3*M) out[256*Ms + i] = 0.f;              // coord_p accumulators
    if (i < M)   out[268*Ms + (size_t)N + i] = 0.f;  // count accumulators (batch_p slot)
}

// zero x region [0, 256*M) floats (encoded 0 sorts below all finite)
__global__ void k_zerox(uint4* __restrict__ x, size_t n4){
    size_t i = (size_t)blockIdx.x*blockDim.x + threadIdx.x;
    size_t stride = (size_t)gridDim.x*blockDim.x;
    uint4 z = make_uint4(0u,0u,0u,0u);
    for (; i < n4; i += stride) x[i] = z;
}

// split W into bf16 hi/lo, plain [c][k] layout
__global__ void k_wt(const float* __restrict__ W){
    int t = blockIdx.x*blockDim.x + threadIdx.x;
    if (t >= 256*128) return;
    float x = W[t];
    __nv_bfloat16 h = __float2bfloat16(x);
    __nv_bfloat16 l = __float2bfloat16(x - __bfloat162float(h));
    g_Whi[t] = h;
    g_Wlo[t] = l;
}

__global__ void k_headmin(const int* __restrict__ code0, int Npts){
    int i = blockIdx.x*blockDim.x + threadIdx.x;
    if (i >= Npts) return;
    int c0 = code0[i] >> 3;
    if (c0 >= 0 && c0 < SLOTS) atomicMin(&g_headmin[c0], i);
}

// single-block scan over slot occupancy -> g_rank, g_headof
__global__ void k_scan_slots(){
    __shared__ int ss[1024];
    int t = threadIdx.x;
    int base = t * (SLOTS/1024);
    int c = 0;
    for (int i = 0; i < SLOTS/1024; i++) c += (g_headmin[base+i] != 0x7fffffff);
    ss[t] = c; __syncthreads();
    int mycnt = c;
    for (int off = 1; off < 1024; off <<= 1){
        int v = (t >= off) ? ss[t-off] : 0;
        __syncthreads();
        ss[t] += v;
        __syncthreads();
    }
    int run = ss[t] - mycnt;
    for (int i = 0; i < SLOTS/1024; i++){
        int s = base + i;
        int h = g_headmin[s];
        if (h != 0x7fffffff){
            g_rank[s] = run;
            g_headof[run] = h;
            run++;
        }
    }
}

__global__ void k_points(const int* __restrict__ code0,
                         const float* __restrict__ coord,
                         float* __restrict__ out, int M, int Npts){
    int i = blockIdx.x*blockDim.x + threadIdx.x;
    if (i >= Npts) return;
    int c0 = code0[i] >> 3;
    int m = 0;
    if (c0 >= 0 && c0 < SLOTS) m = g_rank[c0];
    if (m < 0 || m >= MMAX) m = 0;
    g_cluster[i] = m;
    size_t Ms = (size_t)M;
    out[268*Ms + (size_t)i] = (float)m;              // cluster output
    if (m < M){
        atomicAdd(&out[268*Ms + (size_t)Npts + m], 1.0f);   // count
        size_t ci = 3ull*(size_t)i;
        atomicAdd(&out[256*Ms + 3*(size_t)m+0], coord[ci+0]);
        atomicAdd(&out[256*Ms + 3*(size_t)m+1], coord[ci+1]);
        atomicAdd(&out[256*Ms + 3*(size_t)m+2], coord[ci+2]);
    }
}

__global__ void k_heads(const int* __restrict__ code0,
                        const int* __restrict__ code1,
                        const int* __restrict__ grid_coord,
                        const int* __restrict__ batch,
                        float* __restrict__ out, int M, int Npts){
    int m = blockIdx.x*blockDim.x + threadIdx.x;
    if (m >= M || m >= MMAX) return;
    int h = g_headof[m];
    if (h < 0 || h >= Npts) return;
    size_t Ms = (size_t)M;
    float cf = out[268*Ms + (size_t)Npts + m];        // count (read BEFORE overwrite)
    float inv = 1.0f / cf;
    out[256*Ms + 3*(size_t)m+0] *= inv;               // coord_p = sum / count
    out[256*Ms + 3*(size_t)m+1] *= inv;
    out[256*Ms + 3*(size_t)m+2] *= inv;
    size_t hb = 3ull*(size_t)h;
    out[259*Ms + 3*(size_t)m+0] = (float)(grid_coord[hb+0] >> 1);  // grid_p
    out[259*Ms + 3*(size_t)m+1] = (float)(grid_coord[hb+1] >> 1);
    out[259*Ms + 3*(size_t)m+2] = (float)(grid_coord[hb+2] >> 1);
    int c0h = code0[h] >> 3;
    int c1h = code1[h] >> 3;
    out[262*Ms + m] = (float)c0h;                     // code_h row0
    out[263*Ms + m] = (float)c1h;                     // code_h row1
    out[264*Ms + m] = (float)m;                       // order row0 (identity)
    out[266*Ms + m] = (float)m;                       // inverse row0 (identity)
    out[268*Ms + (size_t)Npts + m] = (float)batch[h]; // batch_p (overwrites count)
    if (c1h >= 0){
        int b = c1h >> 11;                            // c1h < 2^27 -> 16-bit bucket
        if (b < NBUCK){
            g_keys_raw[m] = ((unsigned long long)(unsigned)c1h << 20) | (unsigned)m;
            atomicAdd(&g_hist[b], 1);
        }
    }
}

__global__ void k_scan_hist(){
    __shared__ int ss[1024];
    int t = threadIdx.x;
    int base = t * (NBUCK/1024);
    int c = 0;
    for (int i = 0; i < NBUCK/1024; i++) c += g_hist[base+i];
    ss[t] = c; __syncthreads();
    int mycnt = c;
    for (int off = 1; off < 1024; off <<= 1){
        int v = (t >= off) ? ss[t-off] : 0;
        __syncthreads();
        ss[t] += v;
        __syncthreads();
    }
    int run = ss[t] - mycnt;
    for (int i = 0; i < NBUCK/1024; i++){
        int s = base + i;
        g_off[s]  = run;
        g_off2[s] = run;
        run += g_hist[s];
    }
}

__global__ void k_scatter(int M){
    int m = blockIdx.x*blockDim.x + threadIdx.x;
    if (m >= M || m >= MMAX) return;
    unsigned long long key = g_keys_raw[m];
    int b = (int)(key >> 31);                          // (c1h<<20)>>31 == c1h>>11
    if (b < 0 || b >= NBUCK) return;
    int pos = atomicAdd(&g_off2[b], 1);
    if (pos >= 0 && pos < MMAX) g_keys_sorted[pos] = key;
}

// per-bucket insertion sort (shared staging), writes order/inverse row 1
__global__ void k_bsort(float* __restrict__ out, int M){
    __shared__ unsigned long long sb[40*128];
    int t  = blockIdx.x*128 + threadIdx.x;
    int tl = threadIdx.x;
    if (t >= NBUCK) return;
    int start = g_off[t];
    int cnt   = g_hist[t];
    if (cnt <= 0 || start < 0 || start >= MMAX) return;
    if (cnt > MMAX - start) cnt = MMAX - start;
    size_t offOrd = 265ull*(size_t)M;   // order row1
    size_t offInv = 267ull*(size_t)M;   // inverse row1
    if (cnt <= 40){
        for (int j = 0; j < cnt; j++) sb[j*128+tl] = g_keys_sorted[start+j];
        for (int a = 1; a < cnt; a++){
            unsigned long long x = sb[a*128+tl];
            int b2 = a-1;
            while (b2 >= 0 && sb[b2*128+tl] > x){ sb[(b2+1)*128+tl] = sb[b2*128+tl]; b2--; }
            sb[(b2+1)*128+tl] = x;
        }
        for (int j = 0; j < cnt; j++){
            unsigned long long key = sb[j*128+tl];
            int m = (int)(key & 0xFFFFFull);
            int p = start + j;
            if (p < M)            out[offOrd + p] = (float)m;
            if (m < M && m >= 0)  out[offInv + m] = (float)p;
        }
    } else {
        for (int a = 0; a < cnt; a++){
            int best = a; unsigned long long bk = g_keys_sorted[start+a];
            for (int j = a+1; j < cnt; j++){
                unsigned long long kj = g_keys_sorted[start+j];
                if (kj < bk){ bk = kj; best = j; }
            }
            unsigned long long tmp = g_keys_sorted[start+a];
            g_keys_sorted[start+a] = bk;
            g_keys_sorted[start+best] = tmp;
            int m = (int)(bk & 0xFFFFFull);
            if (start + a < M)    out[offOrd + start + a] = (float)m;
            if (m < M && m >= 0)  out[offInv + m] = (float)(start + a);
        }
    }
}

// ---------------- HMMA GEMM (proj = feat @ W^T + b) + segment-max ----------------
// mma.sync.m16n8k16 bf16 (baseline ISA, no 'a' target needed), fp32 accum.
// bf16 3-product split: D = Ah*Wh + Al*Wh + Ah*Wl  (~1e-5 precision).
// CTA: 128 rows x 128 cols (blockIdx.y selects column half), 8 warps,
// warp tile 32x64 (2 m-frags x 8 n-frags). K chunked 4 x 32.
// smem stride 36 bf16 (=72B) -> conflict-free b32 fragment loads.
#define SSTR 36
__device__ __forceinline__ void mma_bf16(float* d, const unsigned* a, const unsigned* b){
    asm volatile(
        "mma.sync.aligned.m16n8k16.row.col.f32.bf16.bf16.f32 "
        "{%0,%1,%2,%3}, {%4,%5,%6,%7}, {%8,%9}, {%0,%1,%2,%3};"
        : "+f"(d[0]), "+f"(d[1]), "+f"(d[2]), "+f"(d[3])
        : "r"(a[0]), "r"(a[1]), "r"(a[2]), "r"(a[3]), "r"(b[0]), "r"(b[1]));
}

__global__ __launch_bounds__(256) void k_gemm_mma(const float* __restrict__ feat,
                                                  const float* __restrict__ bias,
                                                  unsigned int* __restrict__ xenc,
                                                  int M, int Npts){
    __shared__ __nv_bfloat16 sAh[128*SSTR];
    __shared__ __nv_bfloat16 sAl[128*SSTR];
    __shared__ __nv_bfloat16 sBh[128*SSTR];
    __shared__ __nv_bfloat16 sBl[128*SSTR];
    __shared__ float sBias[128];

    int tid  = threadIdx.x;
    int wid  = tid >> 5, lane = tid & 31;
    int g    = lane >> 2, tc = lane & 3;
    int row0 = blockIdx.x * 128;
    int chalf = blockIdx.y;          // 0 or 1: column half
    int m0w  = (wid >> 1) * 32;      // warp row offset (4 warps vertical)
    int n0w  = (wid & 1) * 64;       // warp col offset (2 warps horizontal)

    if (tid < 128) sBias[tid] = bias[chalf*128 + tid];

    float acc[2][8][4];
#pragma unroll
    for (int mi = 0; mi < 2; mi++)
#pragma unroll
        for (int ni = 0; ni < 8; ni++)
#pragma unroll
            for (int q = 0; q < 4; q++) acc[mi][ni][q] = 0.f;

    for (int kc = 0; kc < 4; kc++){
        __syncthreads();
        // A chunk: 128 rows x 32 k fp32 -> bf16 hi/lo (1024 float4 / 256 thr)
#pragma unroll
        for (int it = 0; it < 4; it++){
            int idx = tid + it*256;
            int r = idx >> 3, q = idx & 7;          // row, float4-quad
            float4 f = *(const float4*)&feat[(size_t)(row0 + r)*128 + kc*32 + q*4];
            __nv_bfloat16 h0 = __float2bfloat16(f.x), h1 = __float2bfloat16(f.y);
            __nv_bfloat16 h2 = __float2bfloat16(f.z), h3 = __float2bfloat16(f.w);
            __nv_bfloat16 l0 = __float2bfloat16(f.x - __bfloat162float(h0));
            __nv_bfloat16 l1 = __float2bfloat16(f.y - __bfloat162float(h1));
            __nv_bfloat16 l2 = __float2bfloat16(f.z - __bfloat162float(h2));
            __nv_bfloat16 l3 = __float2bfloat16(f.w - __bfloat162float(h3));
            int base = r*SSTR + q*4;
            *(__nv_bfloat162*)&sAh[base]   = __halves2bfloat162(h0, h1);
            *(__nv_bfloat162*)&sAh[base+2] = __halves2bfloat162(h2, h3);
            *(__nv_bfloat162*)&sAl[base]   = __halves2bfloat162(l0, l1);
            *(__nv_bfloat162*)&sAl[base+2] = __halves2bfloat162(l2, l3);
        }
        // B chunk: 128 c x 32 k bf16 (2048 b32 loads per image / 256 thr)
#pragma unroll
        for (int it = 0; it < 8; it++){
            int idx = tid + it*256;
            int cl = idx >> 4, pk = idx & 15;       // local c, k-pair
            int src = (chalf*128 + cl)*128 + kc*32 + pk*2;
            int dst = cl*SSTR + pk*2;
            *(__nv_bfloat162*)&sBh[dst] = *(const __nv_bfloat162*)&g_Whi[src];
            *(__nv_bfloat162*)&sBl[dst] = *(const __nv_bfloat162*)&g_Wlo[src];
        }
        __syncthreads();

#pragma unroll
        for (int ks = 0; ks < 2; ks++){
            int kb = ks*16;
            unsigned ah[2][4], al[2][4];
#pragma unroll
            for (int mi = 0; mi < 2; mi++){
                int rA = m0w + mi*16 + g;
                ah[mi][0] = *(const unsigned*)&sAh[rA*SSTR + kb + 2*tc];
                ah[mi][1] = *(const unsigned*)&sAh[(rA+8)*SSTR + kb + 2*tc];
                ah[mi][2] = *(const unsigned*)&sAh[rA*SSTR + kb + 2*tc + 8];
                ah[mi][3] = *(const unsigned*)&sAh[(rA+8)*SSTR + kb + 2*tc + 8];
                al[mi][0] = *(const unsigned*)&sAl[rA*SSTR + kb + 2*tc];
                al[mi][1] = *(const unsigned*)&sAl[(rA+8)*SSTR + kb + 2*tc];
                al[mi][2] = *(const unsigned*)&sAl[rA*SSTR + kb + 2*tc + 8];
                al[mi][3] = *(const unsigned*)&sAl[(rA+8)*SSTR + kb + 2*tc + 8];
            }
#pragma unroll
            for (int ni = 0; ni < 8; ni++){
                int cB = n0w + ni*8 + g;
                unsigned bh[2], bl[2];
                bh[0] = *(const unsigned*)&sBh[cB*SSTR + kb + 2*tc];
                bh[1] = *(const unsigned*)&sBh[cB*SSTR + kb + 2*tc + 8];
                bl[0] = *(const unsigned*)&sBl[cB*SSTR + kb + 2*tc];
                bl[1] = *(const unsigned*)&sBl[cB*SSTR + kb + 2*tc + 8];
#pragma unroll
                for (int mi = 0; mi < 2; mi++){
                    mma_bf16(acc[mi][ni], ah[mi], bh);   // Ah*Wh
                    mma_bf16(acc[mi][ni], al[mi], bh);   // Al*Wh
                    mma_bf16(acc[mi][ni], ah[mi], bl);   // Ah*Wl
                }
            }
        }
    }

    // epilogue: bias + encoded atomicMax into xenc
#pragma unroll
    for (int mi = 0; mi < 2; mi++){
        int r1 = row0 + m0w + mi*16 + g;
        int r2 = r1 + 8;
        int m1 = (r1 < Npts) ? g_cluster[r1] : -1;
        int m2 = (r2 < Npts) ? g_cluster[r2] : -1;
        bool ok1 = (m1 >= 0 && m1 < M), ok2 = (m2 >= 0 && m2 < M);
        unsigned int* p1 = ok1 ? (xenc + (size_t)m1*256 + chalf*128) : xenc;
        unsigned int* p2 = ok2 ? (xenc + (size_t)m2*256 + chalf*128) : xenc;
#pragma unroll
        for (int ni = 0; ni < 8; ni++){
            int c0 = n0w + ni*8 + 2*tc;
            float b0 = sBias[c0], b1 = sBias[c0+1];
            if (ok1){
                atomicMax(p1 + c0,     encf(acc[mi][ni][0] + b0));
                atomicMax(p1 + c0 + 1, encf(acc[mi][ni][1] + b1));
            }
            if (ok2){
                atomicMax(p2 + c0,     encf(acc[mi][ni][2] + b0));
                atomicMax(p2 + c0 + 1, encf(acc[mi][ni][3] + b1));
            }
        }
    }
}

// ---------------- LayerNorm + exact GELU, in place over x region ----------------
__global__ void k_ln(float* __restrict__ out,
                     const float* __restrict__ gamma,
                     const float* __restrict__ beta, int M){
    int w = threadIdx.x >> 5, lane = threadIdx.x & 31;
    int m = blockIdx.x*8 + w;
    if (m >= M) return;
    const unsigned int* src = (const unsigned int*)out + (size_t)m*256;
    float v[8]; float s = 0.f;
#pragma unroll
    for (int j = 0; j < 8; j++){ v[j] = decf(src[lane + 32*j]); s += v[j]; }
#pragma unroll
    for (int o = 16; o; o >>= 1) s += __shfl_xor_sync(0xffffffffu, s, o);
    float mu = s * (1.f/256.f);
    float q = 0.f;
#pragma unroll
    for (int j = 0; j < 8; j++){ float d = v[j]-mu; q += d*d; }
#pragma unroll
    for (int o = 16; o; o >>= 1) q += __shfl_xor_sync(0xffffffffu, q, o);
    float inv = rsqrtf(q*(1.f/256.f) + 1e-5f);
#pragma unroll
    for (int j = 0; j < 8; j++){
        int c = lane + 32*j;
        float y = (v[j]-mu)*inv*gamma[c] + beta[c];
        out[(size_t)m*256 + c] = 0.5f*y*(1.f + erff(y*0.70710678118654752f));
    }
}

// ---------------- launch ----------------
extern "C" void kernel_launch(void* const* d_in, const int* in_sizes, int n_in,
                              void* d_out, int out_size){
    const float* feat  = (const float*)d_in[0];
    const float* coord = (const float*)d_in[1];
    const int*   gridc = (const int*)d_in[2];
    const int*   scode = (const int*)d_in[3];    // int32 (JAX x64-disabled truncation)
    const int*   batch = (const int*)d_in[4];
    int iW = 6;
    for (int i = 5; i < n_in; i++) if (in_sizes[i] == 256*128){ iW = i; break; }
    const float* W     = (const float*)d_in[iW];
    const float* bias  = (const float*)d_in[iW+1];
    const float* gamma = (const float*)d_in[iW+2];
    const float* beta  = (const float*)d_in[iW+3];

    int N = in_sizes[0] / 128;
    int M = (out_size - N) / 269;
    float* out = (float*)d_out;
    const int* code0 = scode;
    const int* code1 = scode + N;

    int Tinit = 3*M > SLOTS ? 3*M : SLOTS;
    k_init<<<(Tinit+255)/256, 256>>>(out, M, N);
    k_zerox<<<2048, 256>>>((uint4*)d_out, (size_t)M*64);
    k_wt<<<128, 256>>>(W);
    k_headmin<<<(N+255)/256, 256>>>(code0, N);
    k_scan_slots<<<1, 1024>>>();
    k_points<<<(N+255)/256, 256>>>(code0, coord, out, M, N);
    k_heads<<<(M+255)/256, 256>>>(code0, code1, gridc, batch, out, M, N);
    k_scan_hist<<<1, 1024>>>();
    k_scatter<<<(M+255)/256, 256>>>(M);
    k_bsort<<<NBUCK/128, 128>>>(out, M);
    k_gemm_mma<<<dim3((N+127)/128, 2), 256>>>(feat, bias, (unsigned int*)d_out, M, N);
    k_ln<<<(M+7)/8, 256>>>(out, gamma, beta, M);
}